// round 3
// baseline (speedup 1.0000x reference)
#include <cuda_runtime.h>
#include <math.h>

// Problem constants
#define N_   256
#define T_   128
#define D_   512
#define H_   1024
#define KTOT 2560          // D + H + H (concat [x_t | h | attn])
#define G4   4096          // 4*H gate columns

// GEMM tiling
#define BM   64            // rows per block
#define BJ   32            // j-columns per block (each j carries 4 gates)
#define KT   32            // K tile

// -------- persistent device scratch (no allocations allowed) --------
__device__ float g_Wcat[KTOT * G4];    // [k][j][g] gate-interleaved concat weights
__device__ float g_b4[G4];             // [j][g]
__device__ float g_h[2][N_ * H_];      // ping-pong hidden state
__device__ float g_c[2][N_ * H_];      // ping-pong cell state
__device__ float g_attn[N_ * H_];      // per-step attention context

// -------- f32x2 packed helpers (sm_100+) --------
__device__ __forceinline__ void fma2(unsigned long long& d,
                                     unsigned long long a,
                                     unsigned long long b) {
    asm("fma.rn.f32x2 %0, %1, %2, %0;" : "+l"(d) : "l"(a), "l"(b));
}
__device__ __forceinline__ unsigned long long dup2(float f) {
    unsigned long long r;
    unsigned u = __float_as_uint(f);
    asm("mov.b64 %0, {%1, %1};" : "=l"(r) : "r"(u));
    return r;
}
__device__ __forceinline__ float2 unpk(unsigned long long v) {
    unsigned lo, hi;
    asm("mov.b64 {%0, %1}, %2;" : "=r"(lo), "=r"(hi) : "l"(v));
    return make_float2(__uint_as_float(lo), __uint_as_float(hi));
}
__device__ __forceinline__ float sigmoidf_(float x) {
    return 1.0f / (1.0f + expf(-x));
}

// -------- prep: reorder W into gate-interleaved [k][j][4] layout --------
__global__ void __launch_bounds__(256) reorder_w_kernel(
    const float* __restrict__ Wx, const float* __restrict__ Wh,
    const float* __restrict__ Wattn) {
    int idx = blockIdx.x * 256 + threadIdx.x;   // idx = k*1024 + j
    if (idx >= KTOT * H_) return;
    int k = idx >> 10;
    int j = idx & 1023;
    const float* row;
    if (k < D_)            row = Wx    + (size_t)k * G4;
    else if (k < D_ + H_)  row = Wh    + (size_t)(k - D_) * G4;
    else                   row = Wattn + (size_t)(k - D_ - H_) * G4;
    float4 v = make_float4(row[j], row[H_ + j], row[2 * H_ + j], row[3 * H_ + j]);
    *(float4*)(g_Wcat + (size_t)idx * 4) = v;
}

__global__ void reorder_b_kernel(const float* __restrict__ b) {
    int idx = blockIdx.x * 256 + threadIdx.x;   // idx = j*4 + g
    if (idx >= G4) return;
    int j = idx >> 2;
    int g = idx & 3;
    g_b4[idx] = b[g * H_ + j];
}

// -------- init: h0 = c0 = mean over 16 spatial locations of A --------
__global__ void __launch_bounds__(256) init_kernel(const float* __restrict__ A) {
    int idx = blockIdx.x * 256 + threadIdx.x;   // idx = n*H + h
    if (idx >= N_ * H_) return;
    const float4* ap = (const float4*)(A + (size_t)idx * 16);
    float4 a0 = ap[0], a1 = ap[1], a2 = ap[2], a3 = ap[3];
    float s = a0.x + a0.y + a0.z + a0.w + a1.x + a1.y + a1.z + a1.w +
              a2.x + a2.y + a2.z + a2.w + a3.x + a3.y + a3.z + a3.w;
    float m = s * (1.0f / 16.0f);
    g_h[0][idx] = m;
    g_c[0][idx] = m;
}

// -------- per-step spatial attention over 16 locations --------
__global__ void __launch_bounds__(256) attn_kernel(const float* __restrict__ A, int cur) {
    __shared__ float sh[H_];
    __shared__ float sred[8][16];
    __shared__ float sw[16];
    int n   = blockIdx.x;
    int tid = threadIdx.x;
    const float* hp = g_h[cur] + (size_t)n * H_;
    ((float4*)sh)[tid] = ((const float4*)hp)[tid];   // 1024 floats / 256 threads
    __syncthreads();

    const float* Ab = A + (size_t)n * H_ * 16;
    float s[16];
#pragma unroll
    for (int p = 0; p < 16; p++) s[p] = 0.0f;
    for (int hh = tid; hh < H_; hh += 256) {
        float hv = sh[hh];
        const float4* ap = (const float4*)(Ab + (size_t)hh * 16);
        float4 a0 = ap[0], a1 = ap[1], a2 = ap[2], a3 = ap[3];
        s[0]  += hv * a0.x; s[1]  += hv * a0.y; s[2]  += hv * a0.z; s[3]  += hv * a0.w;
        s[4]  += hv * a1.x; s[5]  += hv * a1.y; s[6]  += hv * a1.z; s[7]  += hv * a1.w;
        s[8]  += hv * a2.x; s[9]  += hv * a2.y; s[10] += hv * a2.z; s[11] += hv * a2.w;
        s[12] += hv * a3.x; s[13] += hv * a3.y; s[14] += hv * a3.z; s[15] += hv * a3.w;
    }
#pragma unroll
    for (int p = 0; p < 16; p++) {
#pragma unroll
        for (int off = 16; off > 0; off >>= 1)
            s[p] += __shfl_down_sync(0xFFFFFFFF, s[p], off);
    }
    int lane = tid & 31, w = tid >> 5;
    if (lane == 0) {
#pragma unroll
        for (int p = 0; p < 16; p++) sred[w][p] = s[p];
    }
    __syncthreads();
    if (tid == 0) {
        float sc[16];
        float mx = -1e30f;
#pragma unroll
        for (int p = 0; p < 16; p++) {
            float t = 0.0f;
#pragma unroll
            for (int ww = 0; ww < 8; ww++) t += sred[ww][p];
            sc[p] = t * (1.0f / 32.0f);   // 1/sqrt(H), H=1024
            mx = fmaxf(mx, sc[p]);
        }
        float se = 0.0f;
#pragma unroll
        for (int p = 0; p < 16; p++) { sc[p] = expf(sc[p] - mx); se += sc[p]; }
        float inv = 1.0f / se;
#pragma unroll
        for (int p = 0; p < 16; p++) sw[p] = sc[p] * inv;
    }
    __syncthreads();

    float w0  = sw[0],  w1  = sw[1],  w2  = sw[2],  w3  = sw[3];
    float w4  = sw[4],  w5  = sw[5],  w6  = sw[6],  w7  = sw[7];
    float w8  = sw[8],  w9  = sw[9],  w10 = sw[10], w11 = sw[11];
    float w12 = sw[12], w13 = sw[13], w14 = sw[14], w15 = sw[15];
    for (int hh = tid; hh < H_; hh += 256) {
        const float4* ap = (const float4*)(Ab + (size_t)hh * 16);
        float4 a0 = ap[0], a1 = ap[1], a2 = ap[2], a3 = ap[3];
        float acc = a0.x * w0  + a0.y * w1  + a0.z * w2  + a0.w * w3
                  + a1.x * w4  + a1.y * w5  + a1.z * w6  + a1.w * w7
                  + a2.x * w8  + a2.y * w9  + a2.z * w10 + a2.w * w11
                  + a3.x * w12 + a3.y * w13 + a3.z * w14 + a3.w * w15;
        g_attn[(size_t)n * H_ + hh] = acc;
    }
}

// -------- per-step fused GEMM + LSTM gates/state update --------
// grid: (BJ blocks over j = 32, row blocks = 4), 256 threads.
// Each block: rows [rowBase, rowBase+64), j-cols [jBase, jBase+32), all 4 gates.
__global__ void __launch_bounds__(256) step_kernel(
    const float* __restrict__ x, float* __restrict__ out, int t, int cur) {
    __shared__ __align__(16) float aT[KT][BM];        // [k][row]
    __shared__ __align__(16) float wT[KT][BJ * 4];    // [k][j*4+g]

    const int tid  = threadIdx.x;
    const int jIdx = tid & 15;      // 0..15
    const int rg   = tid >> 4;      // 0..15
    const int r0   = rg * 4;
    const int jl   = jIdx * 2;      // local j
    const int jl4  = jl * 4;
    const int rowBase = blockIdx.y * BM;
    const int jBase   = blockIdx.x * BJ;

    const int loadRow = tid >> 2;          // 0..63
    const int kQ      = (tid & 3) * 8;
    const int nLoad   = rowBase + loadRow;

    const float* __restrict__ hprev = g_h[cur];
    const float* __restrict__ attn  = g_attn;

    unsigned long long acc[2][2][4];
#pragma unroll
    for (int a = 0; a < 2; a++)
#pragma unroll
        for (int jj = 0; jj < 2; jj++)
#pragma unroll
            for (int g = 0; g < 4; g++) acc[a][jj][g] = 0ULL;

#pragma unroll 1
    for (int kt = 0; kt < KTOT; kt += KT) {
        // ---- load input tile (transposed) ----
        const float* src;
        int off;
        if (kt < D_) {
            src = x + (size_t)nLoad * T_ * D_ + (size_t)t * D_;
            off = kt;
        } else if (kt < D_ + H_) {
            src = hprev + (size_t)nLoad * H_;
            off = kt - D_;
        } else {
            src = attn + (size_t)nLoad * H_;
            off = kt - D_ - H_;
        }
        float4 v0 = *(const float4*)(src + off + kQ);
        float4 v1 = *(const float4*)(src + off + kQ + 4);
        aT[kQ + 0][loadRow] = v0.x; aT[kQ + 1][loadRow] = v0.y;
        aT[kQ + 2][loadRow] = v0.z; aT[kQ + 3][loadRow] = v0.w;
        aT[kQ + 4][loadRow] = v1.x; aT[kQ + 5][loadRow] = v1.y;
        aT[kQ + 6][loadRow] = v1.z; aT[kQ + 7][loadRow] = v1.w;

        // ---- load weight tile ----
#pragma unroll
        for (int i = 0; i < 4; i++) {
            int idx = tid + i * 256;          // float4 units, 1024 total
            int kk  = idx >> 5;
            int c   = idx & 31;
            float4 wv = *(const float4*)(g_Wcat + (size_t)(kt + kk) * G4 + jBase * 4 + c * 4);
            *(float4*)&wT[kk][c * 4] = wv;
        }
        __syncthreads();

        // ---- compute ----
#pragma unroll
        for (int kk = 0; kk < KT; kk++) {
            ulonglong2 a2 = *(const ulonglong2*)&aT[kk][r0];   // rows (r0,r0+1),(r0+2,r0+3)
            float4 wq0 = *(const float4*)&wT[kk][jl4];
            float4 wq1 = *(const float4*)&wT[kk][jl4 + 4];
            unsigned long long wd0[4], wd1[4];
            wd0[0] = dup2(wq0.x); wd0[1] = dup2(wq0.y);
            wd0[2] = dup2(wq0.z); wd0[3] = dup2(wq0.w);
            wd1[0] = dup2(wq1.x); wd1[1] = dup2(wq1.y);
            wd1[2] = dup2(wq1.z); wd1[3] = dup2(wq1.w);
#pragma unroll
            for (int g = 0; g < 4; g++) {
                fma2(acc[0][0][g], a2.x, wd0[g]);
                fma2(acc[1][0][g], a2.y, wd0[g]);
                fma2(acc[0][1][g], a2.x, wd1[g]);
                fma2(acc[1][1][g], a2.y, wd1[g]);
            }
        }
        __syncthreads();
    }

    // ---- epilogue: gates + state update + output ----
    const float* __restrict__ cprev = g_c[cur];
    float* __restrict__ cnext = g_c[cur ^ 1];
    float* __restrict__ hnext = g_h[cur ^ 1];
#pragma unroll
    for (int jj = 0; jj < 2; jj++) {
        int jg = jBase + jl + jj;
        float4 bv = *(const float4*)&g_b4[jg * 4];
#pragma unroll
        for (int rp = 0; rp < 2; rp++) {
            float2 vi = unpk(acc[rp][jj][0]);
            float2 vf = unpk(acc[rp][jj][1]);
            float2 vo = unpk(acc[rp][jj][2]);
            float2 vg = unpk(acc[rp][jj][3]);
#pragma unroll
            for (int rr = 0; rr < 2; rr++) {
                int n = rowBase + r0 + rp * 2 + rr;
                float ai = (rr ? vi.y : vi.x) + bv.x;
                float af = (rr ? vf.y : vf.x) + bv.y;
                float ao = (rr ? vo.y : vo.x) + bv.z;
                float ag = (rr ? vg.y : vg.x) + bv.w;
                float ig = sigmoidf_(ai);
                float fg = sigmoidf_(af);
                float og = sigmoidf_(ao);
                float gg = tanhf(ag);
                float cold = cprev[(size_t)n * H_ + jg];
                float cn = fg * cold + ig * gg;
                float hn = og * tanhf(cn);
                cnext[(size_t)n * H_ + jg] = cn;
                hnext[(size_t)n * H_ + jg] = hn;
                out[(size_t)n * T_ * H_ + (size_t)t * H_ + jg] = hn;
            }
        }
    }
}

extern "C" void kernel_launch(void* const* d_in, const int* in_sizes, int n_in,
                              void* d_out, int out_size) {
    const float* x     = (const float*)d_in[0];
    const float* A     = (const float*)d_in[1];
    const float* Wx    = (const float*)d_in[2];
    const float* Wh    = (const float*)d_in[3];
    const float* Wattn = (const float*)d_in[4];
    const float* b     = (const float*)d_in[5];
    float* out = (float*)d_out;

    reorder_w_kernel<<<(KTOT * H_ + 255) / 256, 256>>>(Wx, Wh, Wattn);
    reorder_b_kernel<<<(G4 + 255) / 256, 256>>>(b);
    init_kernel<<<(N_ * H_ + 255) / 256, 256>>>(A);

    for (int t = 0; t < T_; t++) {
        int cur = t & 1;
        attn_kernel<<<N_, 256>>>(A, cur);
        step_kernel<<<dim3(H_ / BJ, N_ / BM), 256>>>(x, out, t, cur);
    }
}

// round 6
// speedup vs baseline: 3.2824x; 3.2824x over previous
#include <cuda_runtime.h>
#include <cuda_bf16.h>
#include <math.h>
#include <stdint.h>

// Problem constants
#define N_   256
#define T_   128
#define D_   512
#define H_   1024
#define KTOT 2560          // D + H + H
#define G4   4096          // 4*H gate columns

// GEMM tiling: CTA 128(M) x 64(N), K chunks of 64, 3 bf16-split segments
#define BM_  128
#define BN_  64
#define KC   64
#define SEG_CHUNKS 40      // 2560/64
#define CHUNKS 120         // 3 * 40
#define STAGES 4
#define STAGE_A 16384      // 128 rows * 128B
#define STAGE_B 8192       // 64 rows * 128B
#define STAGE_BYTES (STAGE_A + STAGE_B)
#define GEMM_SMEM (STAGES * STAGE_BYTES)   // 98304

// attn smem layout
#define ASM_W    0
#define ASM_RED  64
#define ASM_A    1024
#define ATTN_SMEM (ASM_A + 16 * 1024 * 4)  // 66560

// ---------------- persistent device scratch ----------------
__device__ __nv_bfloat16 g_xh[N_ * T_ * D_];
__device__ __nv_bfloat16 g_xl[N_ * T_ * D_];
__device__ __nv_bfloat16 g_wth[(size_t)G4 * KTOT];   // [col][k], col = j*4+g
__device__ __nv_bfloat16 g_wtl[(size_t)G4 * KTOT];
__device__ __nv_bfloat16 g_acth[N_ * 2048];          // [n][ h | attn ]
__device__ __nv_bfloat16 g_actl[N_ * 2048];
__device__ float g_h[N_ * H_];
__device__ float g_c[N_ * H_];
__device__ float g_b4[G4];                           // [j][gate]

// ---------------- helpers ----------------
__device__ __forceinline__ uint32_t smem_u32(const void* p) {
    uint32_t a;
    asm("{ .reg .u64 t; cvta.to.shared.u64 t, %1; cvt.u32.u64 %0, t; }" : "=r"(a) : "l"(p));
    return a;
}
__device__ __forceinline__ void cp_async16(uint32_t dst, const void* src) {
    asm volatile("cp.async.cg.shared.global [%0], [%1], 16;" :: "r"(dst), "l"(src));
}
#define CP_COMMIT() asm volatile("cp.async.commit_group;" ::: "memory")
#define CP_WAIT2()  asm volatile("cp.async.wait_group 2;" ::: "memory")

__device__ __forceinline__ void ldsm4(uint32_t& r0, uint32_t& r1, uint32_t& r2, uint32_t& r3,
                                      uint32_t addr) {
    asm volatile("ldmatrix.sync.aligned.m8n8.x4.shared.b16 {%0,%1,%2,%3}, [%4];"
                 : "=r"(r0), "=r"(r1), "=r"(r2), "=r"(r3) : "r"(addr));
}
__device__ __forceinline__ void mma16816(float* c, const uint32_t* a, const uint32_t* b) {
    asm volatile("mma.sync.aligned.m16n8k16.row.col.f32.bf16.bf16.f32 "
                 "{%0,%1,%2,%3}, {%4,%5,%6,%7}, {%8,%9}, {%0,%1,%2,%3};"
                 : "+f"(c[0]), "+f"(c[1]), "+f"(c[2]), "+f"(c[3])
                 : "r"(a[0]), "r"(a[1]), "r"(a[2]), "r"(a[3]), "r"(b[0]), "r"(b[1]));
}
__device__ __forceinline__ float sigmoidf_(float x) { return 1.0f / (1.0f + expf(-x)); }
__device__ __forceinline__ void split_bf16(float v, __nv_bfloat16& hi, __nv_bfloat16& lo) {
    hi = __float2bfloat16_rn(v);
    lo = __float2bfloat16_rn(v - __bfloat162float(hi));
}

// ---------------- prep kernels ----------------
__global__ void __launch_bounds__(256) split_x_kernel(const float* __restrict__ x) {
    int idx = blockIdx.x * 256 + threadIdx.x;
    if (idx >= N_ * T_ * D_) return;
    __nv_bfloat16 hi, lo;
    split_bf16(x[idx], hi, lo);
    g_xh[idx] = hi;
    g_xl[idx] = lo;
}

__global__ void __launch_bounds__(256) split_w_kernel(
    const float* __restrict__ Wx, const float* __restrict__ Wh, const float* __restrict__ Wattn) {
    size_t idx = (size_t)blockIdx.x * 256 + threadIdx.x;
    if (idx >= (size_t)G4 * KTOT) return;
    int col = (int)(idx / KTOT);
    int k   = (int)(idx % KTOT);
    int j = col >> 2, g = col & 3;
    float v;
    if (k < D_)            v = Wx[(size_t)k * G4 + g * H_ + j];
    else if (k < D_ + H_)  v = Wh[(size_t)(k - D_) * G4 + g * H_ + j];
    else                   v = Wattn[(size_t)(k - D_ - H_) * G4 + g * H_ + j];
    __nv_bfloat16 hi, lo;
    split_bf16(v, hi, lo);
    g_wth[idx] = hi;
    g_wtl[idx] = lo;
}

__global__ void prep_b_kernel(const float* __restrict__ b) {
    int idx = blockIdx.x * 256 + threadIdx.x;   // idx = j*4+g
    if (idx >= G4) return;
    g_b4[idx] = b[(idx & 3) * H_ + (idx >> 2)];
}

__global__ void __launch_bounds__(256) init_kernel(const float* __restrict__ A) {
    int idx = blockIdx.x * 256 + threadIdx.x;   // idx = n*H + h
    if (idx >= N_ * H_) return;
    const float4* ap = (const float4*)(A + (size_t)idx * 16);
    float4 a0 = ap[0], a1 = ap[1], a2 = ap[2], a3 = ap[3];
    float s = a0.x + a0.y + a0.z + a0.w + a1.x + a1.y + a1.z + a1.w +
              a2.x + a2.y + a2.z + a2.w + a3.x + a3.y + a3.z + a3.w;
    float m = s * (1.0f / 16.0f);
    g_h[idx] = m;
    g_c[idx] = m;
    int n = idx >> 10, hh = idx & 1023;
    __nv_bfloat16 hi, lo;
    split_bf16(m, hi, lo);
    g_acth[n * 2048 + hh] = hi;
    g_actl[n * 2048 + hh] = lo;
}

// ---------------- per-step attention (one CTA per n) ----------------
__global__ void __launch_bounds__(256) attn_kernel(const float* __restrict__ A) {
    extern __shared__ char smem[];
    float* sw   = (float*)(smem + ASM_W);
    float* sred = (float*)(smem + ASM_RED);
    float* sA   = (float*)(smem + ASM_A);     // [16][1024]
    int n = blockIdx.x, tid = threadIdx.x;

    const float* Ab = A + (size_t)n * H_ * 16;
    const float* hb = g_h + (size_t)n * H_;

    float s[16];
#pragma unroll
    for (int p = 0; p < 16; p++) s[p] = 0.0f;

#pragma unroll
    for (int rr = 0; rr < 4; rr++) {
        int row = tid + rr * 256;
        const float4* ap = (const float4*)(Ab + (size_t)row * 16);
        float4 a0 = ap[0], a1 = ap[1], a2 = ap[2], a3 = ap[3];
        float av[16] = {a0.x, a0.y, a0.z, a0.w, a1.x, a1.y, a1.z, a1.w,
                        a2.x, a2.y, a2.z, a2.w, a3.x, a3.y, a3.z, a3.w};
        float hv = hb[row];
#pragma unroll
        for (int p = 0; p < 16; p++) {
            sA[p * 1024 + row] = av[p];
            s[p] += hv * av[p];
        }
    }
#pragma unroll
    for (int p = 0; p < 16; p++) {
#pragma unroll
        for (int off = 16; off > 0; off >>= 1)
            s[p] += __shfl_down_sync(0xFFFFFFFF, s[p], off);
    }
    int lane = tid & 31, w = tid >> 5;
    if (lane == 0) {
#pragma unroll
        for (int p = 0; p < 16; p++) sred[w * 16 + p] = s[p];
    }
    __syncthreads();
    if (tid == 0) {
        float sc[16], mx = -1e30f;
#pragma unroll
        for (int p = 0; p < 16; p++) {
            float t = 0.0f;
#pragma unroll
            for (int ww = 0; ww < 8; ww++) t += sred[ww * 16 + p];
            sc[p] = t * (1.0f / 32.0f);
            mx = fmaxf(mx, sc[p]);
        }
        float se = 0.0f;
#pragma unroll
        for (int p = 0; p < 16; p++) { sc[p] = expf(sc[p] - mx); se += sc[p]; }
        float inv = 1.0f / se;
#pragma unroll
        for (int p = 0; p < 16; p++) sw[p] = sc[p] * inv;
    }
    __syncthreads();

    float wv[16];
#pragma unroll
    for (int p = 0; p < 16; p++) wv[p] = sw[p];
#pragma unroll
    for (int rr = 0; rr < 4; rr++) {
        int row = tid + rr * 256;
        float acc = 0.0f;
#pragma unroll
        for (int p = 0; p < 16; p++) acc += wv[p] * sA[p * 1024 + row];
        __nv_bfloat16 hi, lo;
        split_bf16(acc, hi, lo);
        g_acth[n * 2048 + 1024 + row] = hi;
        g_actl[n * 2048 + 1024 + row] = lo;
    }
}

// ---------------- per-step GEMM (mma.sync bf16, split 3-pass) + LSTM ----------------
// grid (64, 2): x = N-tile (64 gate cols), y = M-tile (128 rows). 256 threads.
// warps 4(M) x 2(N), warp tile 32x32.
__global__ void __launch_bounds__(256, 1) gemm_step_kernel(float* __restrict__ out, int t) {
    extern __shared__ char smem[];
    uint32_t sb = smem_u32(smem);
    const int tid = threadIdx.x;
    const int rowBase = blockIdx.y * BM_;
    const int colBase = blockIdx.x * BN_;
    const int w = tid >> 5, lane = tid & 31;
    const int wm = w & 3, wn = w >> 2;

    float c[2][4][4];
#pragma unroll
    for (int mi = 0; mi < 2; mi++)
#pragma unroll
        for (int ni = 0; ni < 4; ni++)
#pragma unroll
            for (int q = 0; q < 4; q++) c[mi][ni][q] = 0.0f;

    auto load_stage = [&](int ch) {
        int s = ch & 3;
        int seg = ch / SEG_CHUNKS;               // 0: Ah*Bh, 1: Al*Bh, 2: Ah*Bl
        int kp = (ch % SEG_CHUNKS) * KC;
        const __nv_bfloat16* actp = (seg == 1) ? g_actl : g_acth;
        const __nv_bfloat16* xp   = (seg == 1) ? g_xl : g_xh;
        const __nv_bfloat16* wp   = (seg == 2) ? g_wtl : g_wth;
        uint32_t sa  = sb + s * STAGE_BYTES;
        uint32_t sbb = sa + STAGE_A;
#pragma unroll
        for (int i = 0; i < 4; i++) {
            int o = tid + i * 256;
            int r = o >> 3, kc = o & 7;
            int k = kp + kc * 8;
            const __nv_bfloat16* src = (k < D_)
                ? xp + ((size_t)(rowBase + r) * T_ + t) * D_ + k
                : actp + (size_t)(rowBase + r) * 2048 + (k - D_);
            cp_async16(sa + r * 128 + ((kc ^ (r & 7)) << 4), src);
        }
#pragma unroll
        for (int i = 0; i < 2; i++) {
            int o = tid + i * 256;
            int r = o >> 3, kc = o & 7;
            cp_async16(sbb + r * 128 + ((kc ^ (r & 7)) << 4),
                       wp + (size_t)(colBase + r) * KTOT + kp + kc * 8);
        }
    };

    load_stage(0); CP_COMMIT();
    load_stage(1); CP_COMMIT();
    load_stage(2); CP_COMMIT();

    // ldmatrix lane address components (invariant across chunks)
    const int a_r    = (lane & 15);            // + 32*wm + 16*h
    const int a_ksel = (lane >> 4);            // 0/1 -> k-chunk low/high
    const int b_n    = (lane & 7) + ((lane >> 4) << 3);  // + 32*wn + 16*j
    const int b_ksel = (lane >> 3) & 1;

    for (int ch = 0; ch < CHUNKS; ch++) {
        CP_WAIT2();
        __syncthreads();
        if (ch + 3 < CHUNKS) load_stage(ch + 3);
        CP_COMMIT();

        uint32_t sa  = sb + (ch & 3) * STAGE_BYTES;
        uint32_t sbb = sa + STAGE_A;
#pragma unroll
        for (int s = 0; s < 4; s++) {
            uint32_t a[2][4], b[2][4];
#pragma unroll
            for (int h = 0; h < 2; h++) {
                int r = 32 * wm + 16 * h + a_r;
                int kc = 2 * s + a_ksel;
                ldsm4(a[h][0], a[h][1], a[h][2], a[h][3],
                      sa + r * 128 + ((kc ^ (r & 7)) << 4));
            }
#pragma unroll
            for (int j = 0; j < 2; j++) {
                int n = 32 * wn + 16 * j + b_n;
                int kc = 2 * s + b_ksel;
                ldsm4(b[j][0], b[j][1], b[j][2], b[j][3],
                      sbb + n * 128 + ((kc ^ (n & 7)) << 4));
            }
#pragma unroll
            for (int mi = 0; mi < 2; mi++)
#pragma unroll
                for (int ni = 0; ni < 4; ni++)
                    mma16816(c[mi][ni], a[mi], &b[ni >> 1][(ni & 1) * 2]);
        }
    }

    // ---- stage accumulators through smem (stride 68 floats, 16B-aligned rows) ----
    __syncthreads();
    float* Csm = (float*)smem;                 // [128][68]
    const int g = lane >> 2, tq = lane & 3;
#pragma unroll
    for (int mi = 0; mi < 2; mi++)
#pragma unroll
        for (int ni = 0; ni < 4; ni++) {
            int R = 32 * wm + 16 * mi + g;
            int C = 32 * wn + 8 * ni + 2 * tq;
            *(float2*)&Csm[R * 68 + C]       = make_float2(c[mi][ni][0], c[mi][ni][1]);
            *(float2*)&Csm[(R + 8) * 68 + C] = make_float2(c[mi][ni][2], c[mi][ni][3]);
        }
    __syncthreads();

    // ---- LSTM gate epilogue: 2048 (row, j) pairs, 8 per thread ----
    const int jBase = colBase >> 2;            // 16 j's per CTA
#pragma unroll
    for (int i2 = 0; i2 < 8; i2++) {
        int idx = tid + i2 * 256;
        int row = idx >> 4, jl = idx & 15;
        int n = rowBase + row, jg = jBase + jl;
        float4 v  = *(const float4*)&Csm[row * 68 + jl * 4];
        float4 bv = ((const float4*)g_b4)[jg];
        float ig = sigmoidf_(v.x + bv.x);
        float fg = sigmoidf_(v.y + bv.y);
        float og = sigmoidf_(v.z + bv.z);
        float gg = tanhf(v.w + bv.w);
        size_t hidx = (size_t)n * H_ + jg;
        float cn = fg * g_c[hidx] + ig * gg;
        float hn = og * tanhf(cn);
        g_c[hidx] = cn;
        g_h[hidx] = hn;
        __nv_bfloat16 hi, lo;
        split_bf16(hn, hi, lo);
        g_acth[(size_t)n * 2048 + jg] = hi;
        g_actl[(size_t)n * 2048 + jg] = lo;
        out[((size_t)n * T_ + t) * H_ + jg] = hn;
    }
}

// ---------------- host launch ----------------
extern "C" void kernel_launch(void* const* d_in, const int* in_sizes, int n_in,
                              void* d_out, int out_size) {
    const float* x     = (const float*)d_in[0];
    const float* A     = (const float*)d_in[1];
    const float* Wx    = (const float*)d_in[2];
    const float* Wh    = (const float*)d_in[3];
    const float* Wattn = (const float*)d_in[4];
    const float* b     = (const float*)d_in[5];
    float* out = (float*)d_out;

    cudaFuncSetAttribute(gemm_step_kernel, cudaFuncAttributeMaxDynamicSharedMemorySize, GEMM_SMEM);
    cudaFuncSetAttribute(attn_kernel, cudaFuncAttributeMaxDynamicSharedMemorySize, ATTN_SMEM);

    split_x_kernel<<<(N_ * T_ * D_ + 255) / 256, 256>>>(x);
    split_w_kernel<<<(int)(((size_t)G4 * KTOT + 255) / 256), 256>>>(Wx, Wh, Wattn);
    prep_b_kernel<<<(G4 + 255) / 256, 256>>>(b);
    init_kernel<<<(N_ * H_ + 255) / 256, 256>>>(A);

    for (int t = 0; t < T_; t++) {
        attn_kernel<<<N_, 256, ATTN_SMEM>>>(A);
        gemm_step_kernel<<<dim3(G4 / BN_, N_ / BM_), 256, GEMM_SMEM>>>(out, t);
    }
}